// round 6
// baseline (speedup 1.0000x reference)
#include <cuda_runtime.h>
#include <cstdint>

// ---------------- problem constants ----------------
#define TPB    384         // 256 e1 (mma) workers + 128 decoder workers
#define E1T    256
#define GROUP  28
#define NBLK   147
#define BTOT   4096

#define T_IN   96
#define T_OUTC 32
#define TT     128
#define INF    8
#define H1     64
#define APSTR  76          // A row stride in float2 pairs (conflict-free: 152 ≡ 24 mod 32)
#define ABUF   (32*APSTR*2)   // 4864 floats per A buffer (32 rows of 76 pairs)
#define H1STR  68
#define HD_STR 20

// ---------------- smem layout (float offsets) ----------------
#define OFF_B4   0         // 8*9*4*32 uint4 = 36864 floats (packed tf32 B frags)
#define OFF_A    36864     // 2*4864 = 9728 (double-buffered [x|h] as (hi,lo) pairs)
#define OFF_W2   46592     // 272
#define OFF_W2HB 46864     // 8
#define OFF_G2   46872     // 112
#define OFF_H2   46984     // 28
#define OFF_U    47012     // 28
#define OFF_WD1  47040     // 1280
#define OFF_HD   48320     // 1120
#define OFF_WD2  49440     // 80
#define OFF_G2D  49520     // 112
#define OFF_H2D  49632     // 28
#define OFF_DOUT 49660     // 3584
#define OFF_TMP  53244     // 896
#define SMEM_FLOATS 54140  // 216560 bytes

#define BARSYNC(id,cnt) asm volatile("bar.sync %0, %1;"   :: "r"(id), "r"(cnt) : "memory")
#define BARARR(id,cnt)  asm volatile("bar.arrive %0, %1;" :: "r"(id), "r"(cnt) : "memory")

__device__ __forceinline__ float sigf(float v) {
    return __fdividef(1.0f, 1.0f + __expf(-v));
}
__device__ __forceinline__ float tanhf_fast(float v) {
    return 2.0f * __fdividef(1.0f, 1.0f + __expf(-2.0f * v)) - 1.0f;
}
__device__ __forceinline__ unsigned cvt_tf32(float f) {
    unsigned r; asm("cvt.rna.tf32.f32 %0, %1;" : "=r"(r) : "f"(f)); return r;
}
// produce (hi, lo) tf32 pair for value v
__device__ __forceinline__ float2 tf32_pair(float v) {
    unsigned hi = cvt_tf32(v);
    unsigned lo = cvt_tf32(v - __uint_as_float(hi));
    return make_float2(__uint_as_float(hi), __uint_as_float(lo));
}
__device__ __forceinline__ void mma_tf32(float* c, const unsigned* a, unsigned b0, unsigned b1) {
    asm volatile(
        "mma.sync.aligned.m16n8k8.row.col.f32.tf32.tf32.f32 "
        "{%0,%1,%2,%3}, {%4,%5,%6,%7}, {%8,%9}, {%0,%1,%2,%3};"
        : "+f"(c[0]), "+f"(c[1]), "+f"(c[2]), "+f"(c[3])
        : "r"(a[0]), "r"(a[1]), "r"(a[2]), "r"(a[3]), "r"(b0), "r"(b1));
}

__global__ void __launch_bounds__(TPB, 1)
lstm_net_kernel(const float* __restrict__ x,
                const float* __restrict__ e1Wih, const float* __restrict__ e1Whh, const float* __restrict__ e1b,
                const float* __restrict__ e2Wih, const float* __restrict__ e2Whh, const float* __restrict__ e2b,
                const float* __restrict__ d1Wih, const float* __restrict__ d1Whh, const float* __restrict__ d1b,
                const float* __restrict__ d2Wih, const float* __restrict__ d2Whh, const float* __restrict__ d2b,
                const float* __restrict__ fc1W, const float* __restrict__ fc1b,
                const float* __restrict__ fc2W, const float* __restrict__ fc2b,
                float* __restrict__ out)
{
    extern __shared__ float sm[];
    const int tid  = threadIdx.x;
    const int e0g  = blockIdx.x * GROUP;

    // ================= init =================
    // B fragments, gate-interleaved columns (n' = unit*4 + gate), packed uint4:
    // (bh_rix0, bh_rix1, bl_rix0, bl_rix1)
    if (tid < E1T) {
        const int w = tid >> 5, lane = tid & 31;
        uint4* B4 = (uint4*)(sm + OFF_B4);
        #pragma unroll
        for (int kt = 0; kt < 9; ++kt)
            #pragma unroll
            for (int nt = 0; nt < 4; ++nt) {
                int np = w * 32 + nt * 8 + (lane >> 2);
                int r  = (np & 3) * 64 + (np >> 2);       // W1 row = gate*64 + unit
                unsigned hv[2], lv[2];
                #pragma unroll
                for (int rix = 0; rix < 2; ++rix) {
                    int k = kt * 8 + (lane & 3) + 4 * rix;
                    float v = (k < INF) ? e1Wih[r * INF + k]
                                        : e1Whh[r * H1 + (k - INF)];
                    hv[rix] = cvt_tf32(v);
                    lv[rix] = cvt_tf32(v - __uint_as_float(hv[rix]));
                }
                B4[((w * 9 + kt) * 4 + nt) * 32 + lane] = make_uint4(hv[0], hv[1], lv[0], lv[1]);
            }
    }
    // zero A buffers (h0 = 0, padding)
    for (int idx = tid; idx < 2 * ABUF; idx += TPB) sm[OFF_A + idx] = 0.f;
    // small weights
    for (int idx = tid; idx < 4 * H1; idx += TPB) {
        int g = idx >> 6, k = idx & 63;
        sm[OFF_W2 + g * H1STR + k] = e2Wih[g * H1 + k];
    }
    if (tid < 4) { sm[OFF_W2HB + tid] = e2Whh[tid]; sm[OFF_W2HB + 4 + tid] = e2b[tid]; }
    for (int idx = tid; idx < 64 * 16; idx += TPB) {
        int j = idx >> 4, k = idx & 15;
        sm[OFF_WD1 + j * HD_STR + k] = d1Whh[j * 16 + k];
    }
    if (tid < 64) {
        sm[OFF_WD1 + tid * HD_STR + 16] = d1Wih[tid];
        sm[OFF_WD1 + tid * HD_STR + 17] = d1b[tid];
        int g = tid >> 4, k = tid & 15;
        sm[OFF_WD2 + g * HD_STR + k] = d2Wih[g * 16 + k];
    }
    if (tid < 4) {
        sm[OFF_WD2 + tid * HD_STR + 16] = d2Whh[tid];
        sm[OFF_WD2 + tid * HD_STR + 17] = d2b[tid];
    }
    for (int idx = tid; idx < 2 * GROUP * HD_STR; idx += TPB) sm[OFF_HD + idx] = 0.f;
    if (tid < GROUP) { sm[OFF_H2 + tid] = 0.f; sm[OFF_H2D + tid] = 0.f; }
    __syncthreads();
    // x_0 into A[0] pair-cols 0..7
    if (tid < GROUP * INF) {
        int e = tid >> 3, i = tid & 7;
        int eg = e0g + e; if (eg >= BTOT) eg = BTOT - 1;
        ((float2*)(sm + OFF_A))[e * APSTR + i] = tf32_pair(x[(size_t)eg * (T_IN * INF) + i]);
    }
    __syncthreads();

    if (tid < E1T) {
        // =========================================================
        //         e1 worker group: TF32x3 tensor-core LSTM
        // =========================================================
        const int w = tid >> 5, lane = tid & 31;
        const int gid = lane >> 2, tq = lane & 3;
        const bool qe = ((tq & 1) == 0);

        float bI[4], bF[4], bG[4], bO[4];
        int un[4];
        #pragma unroll
        for (int nt = 0; nt < 4; ++nt) {
            int u = 8 * w + 2 * nt + (tq >> 1);
            un[nt] = u;
            bI[nt] = e1b[u];
            bF[nt] = e1b[64 + u];
            bG[nt] = e1b[128 + u];
            bO[nt] = e1b[192 + u];
        }
        float cs[8];
        #pragma unroll
        for (int i = 0; i < 8; ++i) cs[i] = 0.f;

        const int xe = tid >> 3, xi = tid & 7;
        int xeg = e0g + xe; if (xeg >= BTOT) xeg = BTOT - 1;

        const uint4* __restrict__ B4 = (const uint4*)(sm + OFF_B4);

        for (int t = 0; t < T_IN; ++t) {
            if (t >= 2)      BARSYNC(3 + (t & 1), TPB);
            else if (t == 1) BARSYNC(6, E1T);

            const float2* __restrict__ Ac2 = (const float2*)(sm + OFF_A + (t & 1) * ABUF);
            float2* __restrict__       An2 = (float2*)(sm + OFF_A + ((t + 1) & 1) * ABUF);

            float xv = 0.f;
            if ((t + 1 < T_IN) && tid < GROUP * INF)
                xv = x[(size_t)xeg * (T_IN * INF) + (t + 1) * INF + xi];

            float acc[2][4][4];
            #pragma unroll
            for (int mt = 0; mt < 2; ++mt)
                #pragma unroll
                for (int nt = 0; nt < 4; ++nt)
                    #pragma unroll
                    for (int i = 0; i < 4; ++i) acc[mt][nt][i] = 0.f;

            #pragma unroll
            for (int kt = 0; kt < 9; ++kt) {
                unsigned ah[2][4], al[2][4];
                #pragma unroll
                for (int mt = 0; mt < 2; ++mt) {
                    const float2* ap = Ac2 + (mt * 16 + gid) * APSTR + kt * 8 + tq;
                    float2 p0 = ap[0];
                    float2 p1 = ap[8 * APSTR];
                    float2 p2 = ap[4];
                    float2 p3 = ap[8 * APSTR + 4];
                    ah[mt][0] = __float_as_uint(p0.x); al[mt][0] = __float_as_uint(p0.y);
                    ah[mt][1] = __float_as_uint(p1.x); al[mt][1] = __float_as_uint(p1.y);
                    ah[mt][2] = __float_as_uint(p2.x); al[mt][2] = __float_as_uint(p2.y);
                    ah[mt][3] = __float_as_uint(p3.x); al[mt][3] = __float_as_uint(p3.y);
                }
                #pragma unroll
                for (int nt = 0; nt < 4; ++nt) {
                    uint4 b = B4[((w * 9 + kt) * 4 + nt) * 32 + lane];
                    mma_tf32(acc[0][nt], ah[0], b.x, b.y);   // Ah*Bh
                    mma_tf32(acc[1][nt], ah[1], b.x, b.y);
                    mma_tf32(acc[0][nt], al[0], b.x, b.y);   // Al*Bh
                    mma_tf32(acc[1][nt], al[1], b.x, b.y);
                    mma_tf32(acc[0][nt], ah[0], b.z, b.w);   // Ah*Bl
                    mma_tf32(acc[1][nt], ah[1], b.z, b.w);
                }
            }

            // ---- LSTM cell epilogue: lane-pair gate exchange ----
            #pragma unroll
            for (int mt = 0; mt < 2; ++mt)
                #pragma unroll
                for (int nt = 0; nt < 4; ++nt) {
                    float c0 = acc[mt][nt][0], c1 = acc[mt][nt][1];
                    float c2 = acc[mt][nt][2], c3 = acc[mt][nt][3];
                    float v0 = qe ? c2 : c0, v1 = qe ? c3 : c1;
                    float r0 = __shfl_xor_sync(0xffffffffu, v0, 1);
                    float r1 = __shfl_xor_sync(0xffffffffu, v1, 1);
                    float gi = qe ? c0 : r0;
                    float gf = qe ? c1 : r1;
                    float gg = qe ? r0 : c2;
                    float go = qe ? r1 : c3;
                    int row = mt * 16 + gid + (qe ? 0 : 8);
                    float cc  = cs[mt * 4 + nt];
                    float igv = sigf(gi + bI[nt]);
                    float fgv = sigf(gf + bF[nt]);
                    float ggv = tanhf_fast(gg + bG[nt]);
                    float ogv = sigf(go + bO[nt]);
                    cc = fgv * cc + igv * ggv;
                    cs[mt * 4 + nt] = cc;
                    An2[row * APSTR + 8 + un[nt]] = tf32_pair(ogv * tanhf_fast(cc));
                }
            if ((t + 1 < T_IN) && tid < GROUP * INF)
                An2[xe * APSTR + xi] = tf32_pair(xv);

            BARARR(1 + (t & 1), TPB);                     // h(t) ready
        }
    } else {
        // =========================================================
        //                 decoder worker group (128 thr)
        // =========================================================
        const int dt = tid - E1T;
        const int UD = dt & 15;
        const int EB = dt >> 4;
        float cd[4] = {0.f, 0.f, 0.f, 0.f};
        float c2  = 0.f;
        float c2d = 0.f;
        float d1wi[4], d1wb[4];
        #pragma unroll
        for (int g = 0; g < 4; ++g) {
            int row = (g << 4) + UD;
            d1wi[g] = sm[OFF_WD1 + row * HD_STR + 16];
            d1wb[g] = sm[OFF_WD1 + row * HD_STR + 17];
        }

        int pd = 0;
        for (int t = 0; t < TT; ++t) {
            if (t < T_IN) {
                BARSYNC(1 + (t & 1), TPB);                // wait h(t)
                const float* hb = sm + OFF_A + ((t + 1) & 1) * ABUF;
                float s = 0.f;
                if (dt < 4 * GROUP) {
                    int e = dt >> 2, g = dt & 3;
                    s = sm[OFF_W2HB + 4 + g] + sm[OFF_W2HB + g] * sm[OFF_H2 + e];
                    // h stored as (hi,lo) pairs: pair-cols 8..71 -> float offset 16 + 2u
                    const float4* hr = (const float4*)(hb + e * (2 * APSTR) + 16);
                    const float2* w2 = (const float2*)(sm + OFF_W2 + g * H1STR);
                    #pragma unroll
                    for (int k = 0; k < 32; ++k) {
                        float4 a = hr[k];
                        float2 b = w2[k];
                        s += (a.x + a.y) * b.x + (a.z + a.w) * b.y;
                    }
                }
                BARARR(3 + (t & 1), TPB);                 // done reading h buffer
                if (dt < 4 * GROUP) sm[OFF_G2 + dt] = s;
                BARSYNC(5, TPB - E1T);
                if (dt < GROUP) {
                    float ig = sigf(sm[OFF_G2 + dt * 4 + 0]);
                    float fg = sigf(sm[OFF_G2 + dt * 4 + 1]);
                    float gg = tanhf_fast(sm[OFF_G2 + dt * 4 + 2]);
                    float og = sigf(sm[OFF_G2 + dt * 4 + 3]);
                    c2 = fg * c2 + ig * gg;
                    float h2 = og * tanhf_fast(c2);
                    sm[OFF_H2 + dt] = h2;
                    sm[OFF_U + dt]  = fmaxf(h2, 0.f);
                }
            } else {
                if (dt < GROUP) {
                    int eg = e0g + dt; if (eg >= BTOT) eg = BTOT - 1;
                    sm[OFF_U + dt] = x[(size_t)eg * (T_IN * INF) + (t - 32) * INF];
                }
            }
            BARSYNC(5, TPB - E1T);                        // u ready

            // ---- d1 (in=1, hidden=16) ----
            {
                const float4* hd4 = (const float4*)(sm + OFF_HD) + pd * (GROUP * HD_STR / 4);
                float* hdn = sm + OFF_HD + (1 - pd) * (GROUP * HD_STR);
                #pragma unroll
                for (int m = 0; m < 4; ++m) {
                    int e = EB + 8 * m;
                    if (e < GROUP) {
                        float um = sm[OFF_U + e];
                        float a0 = d1wb[0] + d1wi[0] * um;
                        float a1 = d1wb[1] + d1wi[1] * um;
                        float a2 = d1wb[2] + d1wi[2] * um;
                        float a3 = d1wb[3] + d1wi[3] * um;
                        #pragma unroll
                        for (int k = 0; k < 4; ++k) {
                            float4 av = hd4[e * 5 + k];
                            #pragma unroll
                            for (int g = 0; g < 4; ++g) {
                                const float4 wv = *(const float4*)(sm + OFF_WD1 + ((g << 4) + UD) * HD_STR + 4 * k);
                                float d = av.x * wv.x + av.y * wv.y + av.z * wv.z + av.w * wv.w;
                                if (g == 0) a0 += d; else if (g == 1) a1 += d;
                                else if (g == 2) a2 += d; else a3 += d;
                            }
                        }
                        float ig = sigf(a0), fg = sigf(a1);
                        float gg = tanhf_fast(a2), og = sigf(a3);
                        float c = fg * cd[m] + ig * gg;
                        cd[m] = c;
                        hdn[e * HD_STR + UD] = og * tanhf_fast(c);
                    }
                }
            }
            BARSYNC(5, TPB - E1T);

            // ---- d2 gates ----
            if (dt < 4 * GROUP) {
                int e = dt >> 2, g = dt & 3;
                float s = sm[OFF_WD2 + g * HD_STR + 17]
                        + sm[OFF_WD2 + g * HD_STR + 16] * sm[OFF_H2D + e];
                const float4* hr = (const float4*)(sm + OFF_HD + (1 - pd) * (GROUP * HD_STR) + e * HD_STR);
                #pragma unroll
                for (int k = 0; k < 4; ++k) {
                    float4 a = hr[k];
                    const float4 b = *(const float4*)(sm + OFF_WD2 + g * HD_STR + 4 * k);
                    s += a.x * b.x + a.y * b.y + a.z * b.z + a.w * b.w;
                }
                sm[OFF_G2D + dt] = s;
            }
            BARSYNC(5, TPB - E1T);

            // ---- d2 state -> dout[t] ----
            if (dt < GROUP) {
                float ig = sigf(sm[OFF_G2D + dt * 4 + 0]);
                float fg = sigf(sm[OFF_G2D + dt * 4 + 1]);
                float gg = tanhf_fast(sm[OFF_G2D + dt * 4 + 2]);
                float og = sigf(sm[OFF_G2D + dt * 4 + 3]);
                c2d = fg * c2d + ig * gg;
                float hh = og * tanhf_fast(c2d);
                sm[OFF_H2D + dt]           = hh;
                sm[OFF_DOUT + dt * TT + t] = hh;
            }
            pd ^= 1;
        }
    }
    __syncthreads();

    // ---------------- FC head (all 384 threads) ----------------
    #pragma unroll
    for (int r = 0; r < 3; ++r) {
        int idx = tid + TPB * r;
        if (idx < GROUP * 32) {
            int e = idx >> 5, j = idx & 31;
            float s = fc1b[j];
            const float4* dr = (const float4*)(sm + OFF_DOUT + e * TT);
            const float4* wr = (const float4*)(fc1W + j * TT);
            #pragma unroll 8
            for (int k = 0; k < 32; ++k) {
                float4 a = dr[k], b = wr[k];
                s += a.x * b.x + a.y * b.y + a.z * b.z + a.w * b.w;
            }
            sm[OFF_TMP + e * 32 + j] = s;
        }
    }
    __syncthreads();
    #pragma unroll
    for (int r = 0; r < 3; ++r) {
        int idx = tid + TPB * r;
        if (idx < GROUP * 32) {
            int e = idx >> 5, o = idx & 31;
            if (e0g + e < BTOT) {
                float s = fc2b[o];
                const float4* tr = (const float4*)(sm + OFF_TMP + e * 32);
                const float4* wr = (const float4*)(fc2W + o * 32);
                #pragma unroll
                for (int k = 0; k < 8; ++k) {
                    float4 a = tr[k], b = wr[k];
                    s += a.x * b.x + a.y * b.y + a.z * b.z + a.w * b.w;
                }
                out[(size_t)(e0g + e) * T_OUTC + o] = s;
            }
        }
    }
}

extern "C" void kernel_launch(void* const* d_in, const int* in_sizes, int n_in,
                              void* d_out, int out_size) {
    (void)in_sizes; (void)n_in; (void)out_size;
    const float* x      = (const float*)d_in[0];
    const float* e1Wih  = (const float*)d_in[1];
    const float* e1Whh  = (const float*)d_in[2];
    const float* e1b    = (const float*)d_in[3];
    const float* e2Wih  = (const float*)d_in[4];
    const float* e2Whh  = (const float*)d_in[5];
    const float* e2b    = (const float*)d_in[6];
    const float* d1Wih  = (const float*)d_in[7];
    const float* d1Whh  = (const float*)d_in[8];
    const float* d1b    = (const float*)d_in[9];
    const float* d2Wih  = (const float*)d_in[10];
    const float* d2Whh  = (const float*)d_in[11];
    const float* d2b    = (const float*)d_in[12];
    const float* fc1W   = (const float*)d_in[13];
    const float* fc1b   = (const float*)d_in[14];
    const float* fc2W   = (const float*)d_in[15];
    const float* fc2b   = (const float*)d_in[16];

    const size_t smem = SMEM_FLOATS * sizeof(float);  // 216560 B
    cudaFuncSetAttribute(lstm_net_kernel,
                         cudaFuncAttributeMaxDynamicSharedMemorySize, (int)smem);
    lstm_net_kernel<<<NBLK, TPB, smem>>>(x,
        e1Wih, e1Whh, e1b, e2Wih, e2Whh, e2b,
        d1Wih, d1Whh, d1b, d2Wih, d2Whh, d2b,
        fc1W, fc1b, fc2W, fc2b, (float*)d_out);
}

// round 7
// speedup vs baseline: 1.5664x; 1.5664x over previous
#include <cuda_runtime.h>
#include <cstdint>

// ---------------- problem constants ----------------
#define TPB    384         // 256 e1 (mma) workers + 128 decoder workers
#define E1T    256
#define GROUP  28
#define NBLK   147
#define BTOT   4096

#define T_IN   96
#define T_OUTC 32
#define TT     128
#define INF    8
#define H1     64
#define ASTR   84          // A operand buffer row stride (conflict-free)
#define ABUF   (32*ASTR)   // 2688 floats per A buffer
#define H1STR  68          // e2 weight row stride
#define HD_STR 20

// ---------------- smem layout (float offsets) ----------------
#define OFF_B2   0         // 8*9*4*64 = 18432 (packed tf32 B frags, uint2)
#define OFF_A    18432     // 2*2688 = 5376   (double-buffered [x|h] operand)
#define OFF_W2   23808     // 272
#define OFF_W2HB 24080     // 8
#define OFF_G2   24088     // 112
#define OFF_H2   24200     // 28
#define OFF_U    24228     // 28
#define OFF_WD1  24256     // 1280
#define OFF_HD   25536     // 1120
#define OFF_WD2  26656     // 80
#define OFF_G2D  26736     // 112
#define OFF_H2D  26848     // 28
#define OFF_DOUT 26876     // 3584
#define OFF_TMP  30460     // 896
#define SMEM_FLOATS 31356  // 125424 bytes

#define BARSYNC(id,cnt) asm volatile("bar.sync %0, %1;"   :: "r"(id), "r"(cnt) : "memory")
#define BARARR(id,cnt)  asm volatile("bar.arrive %0, %1;" :: "r"(id), "r"(cnt) : "memory")

__device__ __forceinline__ float sigf(float v) {
    return __fdividef(1.0f, 1.0f + __expf(-v));
}
__device__ __forceinline__ float tanhf_fast(float v) {
    return 2.0f * __fdividef(1.0f, 1.0f + __expf(-2.0f * v)) - 1.0f;
}
__device__ __forceinline__ unsigned cvt_tf32(float f) {
    unsigned r; asm("cvt.rna.tf32.f32 %0, %1;" : "=r"(r) : "f"(f)); return r;
}
__device__ __forceinline__ void mma_tf32(float* c, const unsigned* a, unsigned b0, unsigned b1) {
    asm volatile(
        "mma.sync.aligned.m16n8k8.row.col.f32.tf32.tf32.f32 "
        "{%0,%1,%2,%3}, {%4,%5,%6,%7}, {%8,%9}, {%0,%1,%2,%3};"
        : "+f"(c[0]), "+f"(c[1]), "+f"(c[2]), "+f"(c[3])
        : "r"(a[0]), "r"(a[1]), "r"(a[2]), "r"(a[3]), "r"(b0), "r"(b1));
}

__global__ void __launch_bounds__(TPB, 1)
lstm_net_kernel(const float* __restrict__ x,
                const float* __restrict__ e1Wih, const float* __restrict__ e1Whh, const float* __restrict__ e1b,
                const float* __restrict__ e2Wih, const float* __restrict__ e2Whh, const float* __restrict__ e2b,
                const float* __restrict__ d1Wih, const float* __restrict__ d1Whh, const float* __restrict__ d1b,
                const float* __restrict__ d2Wih, const float* __restrict__ d2Whh, const float* __restrict__ d2b,
                const float* __restrict__ fc1W, const float* __restrict__ fc1b,
                const float* __restrict__ fc2W, const float* __restrict__ fc2b,
                float* __restrict__ out)
{
    extern __shared__ float sm[];
    const int tid  = threadIdx.x;
    const int e0g  = blockIdx.x * GROUP;

    // ================= init =================
    // B fragments (tf32, single precision pass), gate-interleaved: n' = unit*4 + gate
    if (tid < E1T) {
        const int w = tid >> 5, lane = tid & 31;
        uint2* B2 = (uint2*)(sm + OFF_B2);
        #pragma unroll
        for (int kt = 0; kt < 9; ++kt)
            #pragma unroll
            for (int nt = 0; nt < 4; ++nt) {
                int np = w * 32 + nt * 8 + (lane >> 2);
                int r  = (np & 3) * 64 + (np >> 2);       // W1 row = gate*64 + unit
                unsigned hv[2];
                #pragma unroll
                for (int rix = 0; rix < 2; ++rix) {
                    int k = kt * 8 + (lane & 3) + 4 * rix;
                    float v = (k < INF) ? e1Wih[r * INF + k]
                                        : e1Whh[r * H1 + (k - INF)];
                    hv[rix] = cvt_tf32(v);
                }
                B2[((w * 9 + kt) * 4 + nt) * 32 + lane] = make_uint2(hv[0], hv[1]);
            }
    }
    // zero A buffers (padding rows + h0 = 0)
    for (int idx = tid; idx < 2 * ABUF; idx += TPB) sm[OFF_A + idx] = 0.f;
    // small weights
    for (int idx = tid; idx < 4 * H1; idx += TPB) {
        int g = idx >> 6, k = idx & 63;
        sm[OFF_W2 + g * H1STR + k] = e2Wih[g * H1 + k];
    }
    if (tid < 4) { sm[OFF_W2HB + tid] = e2Whh[tid]; sm[OFF_W2HB + 4 + tid] = e2b[tid]; }
    for (int idx = tid; idx < 64 * 16; idx += TPB) {
        int j = idx >> 4, k = idx & 15;
        sm[OFF_WD1 + j * HD_STR + k] = d1Whh[j * 16 + k];
    }
    if (tid < 64) {
        sm[OFF_WD1 + tid * HD_STR + 16] = d1Wih[tid];
        sm[OFF_WD1 + tid * HD_STR + 17] = d1b[tid];
        int g = tid >> 4, k = tid & 15;
        sm[OFF_WD2 + g * HD_STR + k] = d2Wih[g * 16 + k];
    }
    if (tid < 4) {
        sm[OFF_WD2 + tid * HD_STR + 16] = d2Whh[tid];
        sm[OFF_WD2 + tid * HD_STR + 17] = d2b[tid];
    }
    for (int idx = tid; idx < 2 * GROUP * HD_STR; idx += TPB) sm[OFF_HD + idx] = 0.f;
    if (tid < GROUP) { sm[OFF_H2 + tid] = 0.f; sm[OFF_H2D + tid] = 0.f; }
    __syncthreads();
    // x_0 into A[0] cols 0..7
    if (tid < GROUP * INF) {
        int e = tid >> 3, i = tid & 7;
        int eg = e0g + e; if (eg >= BTOT) eg = BTOT - 1;
        sm[OFF_A + e * ASTR + i] = x[(size_t)eg * (T_IN * INF) + i];
    }
    __syncthreads();

    if (tid < E1T) {
        // =========================================================
        //         e1 worker group: TF32 tensor-core LSTM
        // warp w owns B columns [32w, 32w+32) (= units 8w..8w+7, all gates)
        // =========================================================
        const int w = tid >> 5, lane = tid & 31;
        const int gid = lane >> 2, tq = lane & 3;
        const bool qe = ((tq & 1) == 0);

        float bI[4], bF[4], bG[4], bO[4];
        int un[4];
        #pragma unroll
        for (int nt = 0; nt < 4; ++nt) {
            int u = 8 * w + 2 * nt + (tq >> 1);
            un[nt] = u;
            bI[nt] = e1b[u];
            bF[nt] = e1b[64 + u];
            bG[nt] = e1b[128 + u];
            bO[nt] = e1b[192 + u];
        }
        float cs[8];
        #pragma unroll
        for (int i = 0; i < 8; ++i) cs[i] = 0.f;

        const int xe = tid >> 3, xi = tid & 7;   // x loader role (tid<224)
        int xeg = e0g + xe; if (xeg >= BTOT) xeg = BTOT - 1;

        const uint2* __restrict__ B2 = (const uint2*)(sm + OFF_B2);

        for (int t = 0; t < T_IN; ++t) {
            if (t >= 2)      BARSYNC(3 + (t & 1), TPB);   // A-next free (decoder done)
            else if (t == 1) BARSYNC(6, E1T);             // h0/x1 visible within e1

            const float* __restrict__ Ac = sm + OFF_A + (t & 1) * ABUF;
            float* __restrict__       An = sm + OFF_A + ((t + 1) & 1) * ABUF;

            // prefetch next x (hidden under MMA work)
            float xv = 0.f;
            if ((t + 1 < T_IN) && tid < GROUP * INF)
                xv = x[(size_t)xeg * (T_IN * INF) + (t + 1) * INF + xi];

            float acc[2][4][4];
            #pragma unroll
            for (int mt = 0; mt < 2; ++mt)
                #pragma unroll
                for (int nt = 0; nt < 4; ++nt)
                    #pragma unroll
                    for (int i = 0; i < 4; ++i) acc[mt][nt][i] = 0.f;

            #pragma unroll
            for (int kt = 0; kt < 9; ++kt) {
                unsigned ah[2][4];
                #pragma unroll
                for (int mt = 0; mt < 2; ++mt) {
                    const float* ap = Ac + (mt * 16 + gid) * ASTR + kt * 8 + tq;
                    ah[mt][0] = cvt_tf32(ap[0]);
                    ah[mt][1] = cvt_tf32(ap[8 * ASTR]);
                    ah[mt][2] = cvt_tf32(ap[4]);
                    ah[mt][3] = cvt_tf32(ap[8 * ASTR + 4]);
                }
                #pragma unroll
                for (int nt = 0; nt < 4; ++nt) {
                    uint2 b = B2[((w * 9 + kt) * 4 + nt) * 32 + lane];
                    mma_tf32(acc[0][nt], ah[0], b.x, b.y);
                    mma_tf32(acc[1][nt], ah[1], b.x, b.y);
                }
            }

            // ---- LSTM cell epilogue: lane-pair gate exchange ----
            #pragma unroll
            for (int mt = 0; mt < 2; ++mt)
                #pragma unroll
                for (int nt = 0; nt < 4; ++nt) {
                    float c0 = acc[mt][nt][0], c1 = acc[mt][nt][1];
                    float c2 = acc[mt][nt][2], c3 = acc[mt][nt][3];
                    float v0 = qe ? c2 : c0, v1 = qe ? c3 : c1;
                    float r0 = __shfl_xor_sync(0xffffffffu, v0, 1);
                    float r1 = __shfl_xor_sync(0xffffffffu, v1, 1);
                    float gi = qe ? c0 : r0;
                    float gf = qe ? c1 : r1;
                    float gg = qe ? r0 : c2;
                    float go = qe ? r1 : c3;
                    int row = mt * 16 + gid + (qe ? 0 : 8);
                    float cc  = cs[mt * 4 + nt];
                    float igv = sigf(gi + bI[nt]);
                    float fgv = sigf(gf + bF[nt]);
                    float ggv = tanhf_fast(gg + bG[nt]);
                    float ogv = sigf(go + bO[nt]);
                    cc = fgv * cc + igv * ggv;
                    cs[mt * 4 + nt] = cc;
                    An[row * ASTR + 8 + un[nt]] = ogv * tanhf_fast(cc);
                }
            if ((t + 1 < T_IN) && tid < GROUP * INF)
                An[xe * ASTR + xi] = xv;

            BARARR(1 + (t & 1), TPB);                     // h(t) ready
        }
    } else {
        // =========================================================
        //                 decoder worker group (128 thr)
        // =========================================================
        const int dt = tid - E1T;
        const int UD = dt & 15;
        const int EB = dt >> 4;
        float cd[4] = {0.f, 0.f, 0.f, 0.f};
        float c2  = 0.f;
        float c2d = 0.f;
        float d1wi[4], d1wb[4];
        #pragma unroll
        for (int g = 0; g < 4; ++g) {
            int row = (g << 4) + UD;
            d1wi[g] = sm[OFF_WD1 + row * HD_STR + 16];
            d1wb[g] = sm[OFF_WD1 + row * HD_STR + 17];
        }

        int pd = 0;
        for (int t = 0; t < TT; ++t) {
            if (t < T_IN) {
                BARSYNC(1 + (t & 1), TPB);                // wait h(t)
                const float* hb = sm + OFF_A + ((t + 1) & 1) * ABUF;  // h_t at cols 8..71
                float s = 0.f;
                if (dt < 4 * GROUP) {
                    int e = dt >> 2, g = dt & 3;
                    s = sm[OFF_W2HB + 4 + g] + sm[OFF_W2HB + g] * sm[OFF_H2 + e];
                    const float4* hr = (const float4*)(hb + e * ASTR + 8);
                    const float4* w2 = (const float4*)(sm + OFF_W2 + g * H1STR);
                    #pragma unroll
                    for (int k = 0; k < 16; ++k) {
                        float4 a = hr[k], b = w2[k];
                        s += a.x * b.x + a.y * b.y + a.z * b.z + a.w * b.w;
                    }
                }
                BARARR(3 + (t & 1), TPB);                 // done reading h buffer
                if (dt < 4 * GROUP) sm[OFF_G2 + dt] = s;
                BARSYNC(5, TPB - E1T);
                if (dt < GROUP) {
                    float ig = sigf(sm[OFF_G2 + dt * 4 + 0]);
                    float fg = sigf(sm[OFF_G2 + dt * 4 + 1]);
                    float gg = tanhf_fast(sm[OFF_G2 + dt * 4 + 2]);
                    float og = sigf(sm[OFF_G2 + dt * 4 + 3]);
                    c2 = fg * c2 + ig * gg;
                    float h2 = og * tanhf_fast(c2);
                    sm[OFF_H2 + dt] = h2;
                    sm[OFF_U + dt]  = fmaxf(h2, 0.f);
                }
            } else {
                if (dt < GROUP) {
                    int eg = e0g + dt; if (eg >= BTOT) eg = BTOT - 1;
                    sm[OFF_U + dt] = x[(size_t)eg * (T_IN * INF) + (t - 32) * INF];
                }
            }
            BARSYNC(5, TPB - E1T);                        // u ready

            // ---- d1 (in=1, hidden=16) ----
            {
                const float4* hd4 = (const float4*)(sm + OFF_HD) + pd * (GROUP * HD_STR / 4);
                float* hdn = sm + OFF_HD + (1 - pd) * (GROUP * HD_STR);
                #pragma unroll
                for (int m = 0; m < 4; ++m) {
                    int e = EB + 8 * m;
                    if (e < GROUP) {
                        float um = sm[OFF_U + e];
                        float a0 = d1wb[0] + d1wi[0] * um;
                        float a1 = d1wb[1] + d1wi[1] * um;
                        float a2 = d1wb[2] + d1wi[2] * um;
                        float a3 = d1wb[3] + d1wi[3] * um;
                        #pragma unroll
                        for (int k = 0; k < 4; ++k) {
                            float4 av = hd4[e * 5 + k];
                            #pragma unroll
                            for (int g = 0; g < 4; ++g) {
                                const float4 wv = *(const float4*)(sm + OFF_WD1 + ((g << 4) + UD) * HD_STR + 4 * k);
                                float d = av.x * wv.x + av.y * wv.y + av.z * wv.z + av.w * wv.w;
                                if (g == 0) a0 += d; else if (g == 1) a1 += d;
                                else if (g == 2) a2 += d; else a3 += d;
                            }
                        }
                        float ig = sigf(a0), fg = sigf(a1);
                        float gg = tanhf_fast(a2), og = sigf(a3);
                        float c = fg * cd[m] + ig * gg;
                        cd[m] = c;
                        hdn[e * HD_STR + UD] = og * tanhf_fast(c);
                    }
                }
            }
            BARSYNC(5, TPB - E1T);

            // ---- d2 gates ----
            if (dt < 4 * GROUP) {
                int e = dt >> 2, g = dt & 3;
                float s = sm[OFF_WD2 + g * HD_STR + 17]
                        + sm[OFF_WD2 + g * HD_STR + 16] * sm[OFF_H2D + e];
                const float4* hr = (const float4*)(sm + OFF_HD + (1 - pd) * (GROUP * HD_STR) + e * HD_STR);
                #pragma unroll
                for (int k = 0; k < 4; ++k) {
                    float4 a = hr[k];
                    const float4 b = *(const float4*)(sm + OFF_WD2 + g * HD_STR + 4 * k);
                    s += a.x * b.x + a.y * b.y + a.z * b.z + a.w * b.w;
                }
                sm[OFF_G2D + dt] = s;
            }
            BARSYNC(5, TPB - E1T);

            // ---- d2 state -> dout[t] ----
            if (dt < GROUP) {
                float ig = sigf(sm[OFF_G2D + dt * 4 + 0]);
                float fg = sigf(sm[OFF_G2D + dt * 4 + 1]);
                float gg = tanhf_fast(sm[OFF_G2D + dt * 4 + 2]);
                float og = sigf(sm[OFF_G2D + dt * 4 + 3]);
                c2d = fg * c2d + ig * gg;
                float hh = og * tanhf_fast(c2d);
                sm[OFF_H2D + dt]           = hh;
                sm[OFF_DOUT + dt * TT + t] = hh;
            }
            pd ^= 1;
        }
    }
    __syncthreads();

    // ---------------- FC head (all 384 threads) ----------------
    #pragma unroll
    for (int r = 0; r < 3; ++r) {
        int idx = tid + TPB * r;
        if (idx < GROUP * 32) {
            int e = idx >> 5, j = idx & 31;
            float s = fc1b[j];
            const float4* dr = (const float4*)(sm + OFF_DOUT + e * TT);
            const float4* wr = (const float4*)(fc1W + j * TT);
            #pragma unroll 8
            for (int k = 0; k < 32; ++k) {
                float4 a = dr[k], b = wr[k];
                s += a.x * b.x + a.y * b.y + a.z * b.z + a.w * b.w;
            }
            sm[OFF_TMP + e * 32 + j] = s;
        }
    }
    __syncthreads();
    #pragma unroll
    for (int r = 0; r < 3; ++r) {
        int idx = tid + TPB * r;
        if (idx < GROUP * 32) {
            int e = idx >> 5, o = idx & 31;
            if (e0g + e < BTOT) {
                float s = fc2b[o];
                const float4* tr = (const float4*)(sm + OFF_TMP + e * 32);
                const float4* wr = (const float4*)(fc2W + o * 32);
                #pragma unroll
                for (int k = 0; k < 8; ++k) {
                    float4 a = tr[k], b = wr[k];
                    s += a.x * b.x + a.y * b.y + a.z * b.z + a.w * b.w;
                }
                out[(size_t)(e0g + e) * T_OUTC + o] = s;
            }
        }
    }
}

extern "C" void kernel_launch(void* const* d_in, const int* in_sizes, int n_in,
                              void* d_out, int out_size) {
    (void)in_sizes; (void)n_in; (void)out_size;
    const float* x      = (const float*)d_in[0];
    const float* e1Wih  = (const float*)d_in[1];
    const float* e1Whh  = (const float*)d_in[2];
    const float* e1b    = (const float*)d_in[3];
    const float* e2Wih  = (const float*)d_in[4];
    const float* e2Whh  = (const float*)d_in[5];
    const float* e2b    = (const float*)d_in[6];
    const float* d1Wih  = (const float*)d_in[7];
    const float* d1Whh  = (const float*)d_in[8];
    const float* d1b    = (const float*)d_in[9];
    const float* d2Wih  = (const float*)d_in[10];
    const float* d2Whh  = (const float*)d_in[11];
    const float* d2b    = (const float*)d_in[12];
    const float* fc1W   = (const float*)d_in[13];
    const float* fc1b   = (const float*)d_in[14];
    const float* fc2W   = (const float*)d_in[15];
    const float* fc2b   = (const float*)d_in[16];

    const size_t smem = SMEM_FLOATS * sizeof(float);  // 125424 B
    cudaFuncSetAttribute(lstm_net_kernel,
                         cudaFuncAttributeMaxDynamicSharedMemorySize, (int)smem);
    lstm_net_kernel<<<NBLK, TPB, smem>>>(x,
        e1Wih, e1Whh, e1b, e2Wih, e2Whh, e2b,
        d1Wih, d1Whh, d1b, d2Wih, d2Whh, d2b,
        fc1W, fc1b, fc2W, fc2b, (float*)d_out);
}